// round 6
// baseline (speedup 1.0000x reference)
#include <cuda_runtime.h>
#include <cuda_bf16.h>

#define TPAD   192
#define CCH    80
#define NSEG   7
#define SGRID  64
#define MINSEG 19
#define NV8    10              // 32-byte chunks per row (80 floats = 10 x 8)
#define ROWV8  (TPAD * NV8)    // 1920 chunks per batch
#define MAXROWS 128            // MAX_LEN_SEQ

// x is read-only and re-read across graph replays: keep it in L2.
// sm_103: eviction hints require 256-bit (.v4.b64) accesses.
__device__ __forceinline__ ulonglong4 ldg256_evict_last(const ulonglong4* p) {
    ulonglong4 v;
    asm volatile("ld.global.nc.L2::evict_last.v4.b64 {%0,%1,%2,%3}, [%4];"
                 : "=l"(v.x), "=l"(v.y), "=l"(v.z), "=l"(v.w) : "l"(p));
    return v;
}
// out is write-once, never re-read: don't let it pollute L2.
__device__ __forceinline__ void stg256_evict_first(ulonglong4* p, ulonglong4 v) {
    asm volatile("st.global.L2::evict_first.v4.b64 [%0], {%1,%2,%3,%4};"
                 :: "l"(p), "l"(v.x), "l"(v.y), "l"(v.z), "l"(v.w) : "memory");
}

__device__ __forceinline__ float4 u2f4(unsigned long long lo, unsigned long long hi) {
    return make_float4(__uint_as_float((unsigned)(lo & 0xffffffffull)),
                       __uint_as_float((unsigned)(lo >> 32)),
                       __uint_as_float((unsigned)(hi & 0xffffffffull)),
                       __uint_as_float((unsigned)(hi >> 32)));
}
__device__ __forceinline__ unsigned long long f22u(float a, float b) {
    return (unsigned long long)__float_as_uint(a)
         | ((unsigned long long)__float_as_uint(b) << 32);
}

__global__ __launch_bounds__(512)
void interp_lnr_kernel(const float* __restrict__ x,
                       const int*   __restrict__ len_seq,
                       const float* __restrict__ scales,
                       const int*   __restrict__ len_seg_raw,
                       float*       __restrict__ out)
{
    const int b   = blockIdx.x;
    const int tid = threadIdx.x;

    __shared__ float4 s_x[MAXROWS * 2 * NV8];   // 40 KB staged x rows
    __shared__ float s_scale[NSEG];
    __shared__ int   s_lenseg[NSEG];
    __shared__ int   s_off[NSEG];
    __shared__ int   s_cnt[NSEG];
    __shared__ int   s_base[NSEG];
    __shared__ int   s_wcnt[14];
    __shared__ int   s_src[TPAD];
    __shared__ float s_lam[TPAD];

    const ulonglong4* __restrict__ xb =
        (const ulonglong4*)(x + (size_t)b * TPAD * CCH);

    // ---- Stage the live x rows linearly into smem (issued first, in flight
    //      while the plan phase runs). Live src <= len_seq-2, so rows
    //      [0, len_seq-1] suffice. ----
    const int nrows   = min(len_seq[b], MAXROWS);
    const int nchunks = nrows * NV8;
    for (int e = tid; e < nchunks; e += 512) {
        const ulonglong4 v = ldg256_evict_last(&xb[e]);
        s_x[2 * e]     = u2f4(v.x, v.y);
        s_x[2 * e + 1] = u2f4(v.z, v.w);
    }

    // ---- Plan phase (parallel, ballot-based) ----
    if (tid < TPAD) { s_src[tid] = -1; s_lam[tid] = 0.0f; }
    if (tid < NSEG) {
        s_scale[tid]  = scales[b * NSEG + tid] + 0.5f;
        s_lenseg[tid] = len_seg_raw[b * NSEG + tid] + MINSEG;
    }
    __syncthreads();

    if (tid == 0) {
        int acc = 0;
        #pragma unroll
        for (int s = 0; s < NSEG; s++) { s_off[s] = acc; acc += s_lenseg[s]; }
    }
    __syncthreads();

    // Slot (s,i) for tid < 448; count masked prefix via ballot.
    // Both mask terms are integer comparisons on exactly-representable floats.
    if (tid < NSEG * SGRID) {
        const int s = tid >> 6;
        const int i = tid & 63;
        const int lim = min(s_lenseg[s] - 1, nrows - 1 - s_off[s]);
        const float v = __fdiv_rn((float)i, s_scale[s]);   // IEEE RN, matches JAX
        const bool m = (lim > 0) && (floorf(v) < (float)lim);
        const unsigned bal = __ballot_sync(0xffffffffu, m);
        if ((tid & 31) == 0) s_wcnt[tid >> 5] = __popc(bal);
    }
    __syncthreads();

    if (tid == 0) {
        int acc = 0;
        #pragma unroll
        for (int s = 0; s < NSEG; s++) {
            const int cnt = s_wcnt[2 * s] + s_wcnt[2 * s + 1];
            s_base[s] = acc; s_cnt[s] = cnt; acc += cnt;
        }
    }
    __syncthreads();

    // Fill compact table (masked slots of a segment are a prefix of i).
    if (tid < NSEG * SGRID) {
        const int s = tid >> 6;
        const int i = tid & 63;
        if (i < s_cnt[s]) {
            const int p = s_base[s] + i;
            if (p < TPAD) {                      // pos >= 192 dropped by reference
                const float v  = __fdiv_rn((float)i, s_scale[s]);
                const float fl = floorf(v);
                s_src[p] = (int)fl + s_off[s];   // live src <= nrows-2, no clamp needed
                s_lam[p] = v - fl;
            }
        }
    }
    __syncthreads();   // covers both plan tables and staged s_x

    ulonglong4* __restrict__ ob =
        (ulonglong4*)(out + (size_t)b * TPAD * CCH);

    // ---- Stream phase: LDS -> FMA -> linear STG.256(evict_first) only ----
    for (int e = tid; e < ROWV8; e += 512) {
        const int row = e / NV8;
        const int q   = e - row * NV8;
        const int   src = s_src[row];
        const float lam = s_lam[row];
        ulonglong4 r = make_ulonglong4(0ull, 0ull, 0ull, 0ull);
        if (src >= 0) {
            const int ia = (src * NV8 + q) * 2;
            const float4 a0 = s_x[ia];
            const float4 a1 = s_x[ia + 1];
            const float4 c0 = s_x[ia + 2 * NV8];
            const float4 c1 = s_x[ia + 2 * NV8 + 1];
            const float r0x = fmaf(lam, c0.x - a0.x, a0.x);
            const float r0y = fmaf(lam, c0.y - a0.y, a0.y);
            const float r0z = fmaf(lam, c0.z - a0.z, a0.z);
            const float r0w = fmaf(lam, c0.w - a0.w, a0.w);
            const float r1x = fmaf(lam, c1.x - a1.x, a1.x);
            const float r1y = fmaf(lam, c1.y - a1.y, a1.y);
            const float r1z = fmaf(lam, c1.z - a1.z, a1.z);
            const float r1w = fmaf(lam, c1.w - a1.w, a1.w);
            r.x = f22u(r0x, r0y);
            r.y = f22u(r0z, r0w);
            r.z = f22u(r1x, r1y);
            r.w = f22u(r1z, r1w);
        }
        stg256_evict_first(&ob[e], r);
    }
}

extern "C" void kernel_launch(void* const* d_in, const int* in_sizes, int n_in,
                              void* d_out, int out_size)
{
    const float* x           = (const float*)d_in[0];
    const int*   len_seq     = (const int*)  d_in[1];
    const float* scales      = (const float*)d_in[2];
    const int*   len_seg_raw = (const int*)  d_in[3];
    float*       out         = (float*)d_out;

    const int B = in_sizes[1];
    interp_lnr_kernel<<<B, 512>>>(x, len_seq, scales, len_seg_raw, out);
}

// round 7
// speedup vs baseline: 1.0081x; 1.0081x over previous
#include <cuda_runtime.h>
#include <cuda_bf16.h>

#define TPAD   192
#define CCH    80
#define NSEG   7
#define SGRID  64
#define MINSEG 19
#define NV8    10              // 32-byte chunks per row (80 floats = 10 x 8)
#define ROWV8  (TPAD * NV8)    // 1920 chunks per batch
#define NTHR   384             // 1920 / 384 = 5 exact iterations

// x is read-only and re-read across graph replays: keep it in L2.
// sm_103: eviction hints require 256-bit (.v4.b64) accesses.
__device__ __forceinline__ ulonglong4 ldg256_evict_last(const ulonglong4* p) {
    ulonglong4 v;
    asm volatile("ld.global.nc.L2::evict_last.v4.b64 {%0,%1,%2,%3}, [%4];"
                 : "=l"(v.x), "=l"(v.y), "=l"(v.z), "=l"(v.w) : "l"(p));
    return v;
}
// out is write-once, never re-read: don't let it pollute L2.
__device__ __forceinline__ void stg256_evict_first(ulonglong4* p, ulonglong4 v) {
    asm volatile("st.global.L2::evict_first.v4.b64 [%0], {%1,%2,%3,%4};"
                 :: "l"(p), "l"(v.x), "l"(v.y), "l"(v.z), "l"(v.w) : "memory");
}

__device__ __forceinline__ float2 u2f2(unsigned long long u) {
    float2 f;
    f.x = __uint_as_float((unsigned)(u & 0xffffffffull));
    f.y = __uint_as_float((unsigned)(u >> 32));
    return f;
}
__device__ __forceinline__ unsigned long long f22u(float2 f) {
    return (unsigned long long)__float_as_uint(f.x)
         | ((unsigned long long)__float_as_uint(f.y) << 32);
}
__device__ __forceinline__ unsigned long long lerp64(unsigned long long ua,
                                                     unsigned long long uc,
                                                     float lam) {
    const float2 a = u2f2(ua), c = u2f2(uc);
    float2 r;
    r.x = fmaf(lam, c.x - a.x, a.x);
    r.y = fmaf(lam, c.y - a.y, a.y);
    return f22u(r);
}

__global__ __launch_bounds__(NTHR, 5)
void interp_lnr_kernel(const float* __restrict__ x,
                       const int*   __restrict__ len_seq,
                       const float* __restrict__ scales,
                       const int*   __restrict__ len_seg_raw,
                       float*       __restrict__ out)
{
    const int b   = blockIdx.x;
    const int tid = threadIdx.x;

    __shared__ float s_scale[NSEG];
    __shared__ int   s_lenseg[NSEG];
    __shared__ int   s_off[NSEG];
    __shared__ int   s_cnt[NSEG];
    __shared__ int   s_base[NSEG];
    __shared__ int   s_wcnt[14];       // 14 warps' popc over 448 slots
    __shared__ int   s_src[TPAD];
    __shared__ float s_lam[TPAD];

    // Pre-fill: pad rows get src = -1, lam = 0 (overwritten for live rows).
    if (tid < TPAD) { s_src[tid] = -1; s_lam[tid] = 0.0f; }

    if (tid < NSEG) {
        s_scale[tid]  = scales[b * NSEG + tid] + 0.5f;
        s_lenseg[tid] = len_seg_raw[b * NSEG + tid] + MINSEG;
    }
    __syncthreads();

    if (tid == 0) {
        int acc = 0;
        #pragma unroll
        for (int s = 0; s < NSEG; s++) { s_off[s] = acc; acc += s_lenseg[s]; }
    }
    __syncthreads();

    // Parallel mask evaluation over 448 slots, two passes with 384 threads.
    // Both mask terms are integer comparisons on exactly-representable floats.
    {
        const int lseq = len_seq[b];
        #pragma unroll
        for (int pass = 0; pass < 2; pass++) {
            const int slot = tid + pass * NTHR;
            if (slot < NSEG * SGRID && (pass == 0 || tid < NSEG * SGRID - NTHR)) {
                const int s = slot >> 6;
                const int i = slot & 63;
                const int lim = min(s_lenseg[s] - 1, lseq - 1 - s_off[s]);
                const float v = __fdiv_rn((float)i, s_scale[s]); // IEEE RN, matches JAX
                const bool m = (lim > 0) && (floorf(v) < (float)lim);
                const unsigned bal = __ballot_sync(0xffffffffu, m);
                if ((slot & 31) == 0) s_wcnt[slot >> 5] = __popc(bal);
            }
        }
    }
    __syncthreads();

    if (tid == 0) {
        int acc = 0;
        #pragma unroll
        for (int s = 0; s < NSEG; s++) {
            const int cnt = s_wcnt[2 * s] + s_wcnt[2 * s + 1];
            s_base[s] = acc; s_cnt[s] = cnt; acc += cnt;
        }
    }
    __syncthreads();

    // Fill compact table (masked slots of a segment are a prefix of i).
    #pragma unroll
    for (int pass = 0; pass < 2; pass++) {
        const int slot = tid + pass * NTHR;
        if (slot < NSEG * SGRID) {
            const int s = slot >> 6;
            const int i = slot & 63;
            if (i < s_cnt[s]) {
                const int p = s_base[s] + i;
                if (p < TPAD) {                  // pos >= 192 dropped by reference
                    const float v  = __fdiv_rn((float)i, s_scale[s]);
                    const float fl = floorf(v);
                    s_src[p] = min((int)fl + s_off[s], TPAD - 2);
                    s_lam[p] = v - fl;
                }
            }
        }
    }
    __syncthreads();

    const ulonglong4* __restrict__ xb =
        (const ulonglong4*)(x + (size_t)b * TPAD * CCH);
    ulonglong4* __restrict__ ob =
        (ulonglong4*)(out + (size_t)b * TPAD * CCH);

    // Stream: exactly 5 chunks per thread, no boundary predicates.
    #pragma unroll
    for (int k = 0; k < 5; k++) {
        const int e   = tid + k * NTHR;
        const int row = e / NV8;
        const int q   = e - row * NV8;
        const int   src = s_src[row];
        const float lam = s_lam[row];
        ulonglong4 r = make_ulonglong4(0ull, 0ull, 0ull, 0ull);
        if (src >= 0) {
            const ulonglong4 a = ldg256_evict_last(&xb[src * NV8 + q]);
            const ulonglong4 c = ldg256_evict_last(&xb[src * NV8 + NV8 + q]);
            r.x = lerp64(a.x, c.x, lam);
            r.y = lerp64(a.y, c.y, lam);
            r.z = lerp64(a.z, c.z, lam);
            r.w = lerp64(a.w, c.w, lam);
        }
        stg256_evict_first(&ob[e], r);
    }
}

extern "C" void kernel_launch(void* const* d_in, const int* in_sizes, int n_in,
                              void* d_out, int out_size)
{
    const float* x           = (const float*)d_in[0];
    const int*   len_seq     = (const int*)  d_in[1];
    const float* scales      = (const float*)d_in[2];
    const int*   len_seg_raw = (const int*)  d_in[3];
    float*       out         = (float*)d_out;

    const int B = in_sizes[1];
    interp_lnr_kernel<<<B, NTHR>>>(x, len_seq, scales, len_seg_raw, out);
}